// round 5
// baseline (speedup 1.0000x reference)
#include <cuda_runtime.h>
#include <cuda_bf16.h>
#include <cstdint>

// ============================================================================
// Hybrid attention pipeline (sm_103 generic target; no tcgen05 in toolchain):
//  - mma path: C = Ahi*Bhi + Ahi*Blo + Alo*Bhi (bf16 m16n8k16, fp32 acc)
//    -> saturates the tensor pipe at its legacy-mma ceiling (~512 MAC/cyc/SM).
//  - SIMT path: plain fp32 FFMA SGEMM on a 25% tile slice -> uses the
//    otherwise-idle fma pipe concurrently (CTA-level split in one launch).
// Phases: convert -> QKV -> QK -> softmax -> PV. All GEMMs NT; V stored
// transposed. fp32 copies (g_Qf/g_Kf/g_Vtf, probs in g_S) feed SIMT CTAs.
// ============================================================================

using bf16 = __nv_bfloat16;

// ---------------- scratch (device globals; no runtime allocation) -----------
__device__ __align__(256) bf16 g_xhi[8192 * 1024], g_xlo[8192 * 1024];
__device__ __align__(256) bf16 g_Whi[3 * 1024 * 1024], g_Wlo[3 * 1024 * 1024];
__device__ __align__(256) bf16 g_Qhi[8192 * 1024], g_Qlo[8192 * 1024];
__device__ __align__(256) bf16 g_Khi[8192 * 1024], g_Klo[8192 * 1024];
__device__ __align__(256) bf16 g_Vthi[4 * 1024 * 2048], g_Vtlo[4 * 1024 * 2048];
__device__ __align__(256) float g_Qf[8192 * 1024], g_Kf[8192 * 1024];
__device__ __align__(256) float g_Vtf[4 * 1024 * 2048];
__device__ __align__(256) float g_S[4 * 2048 * 2048];
__device__ __align__(256) bf16 g_Phi[4 * 2048 * 2048], g_Plo[4 * 2048 * 2048];

// SIMT tile-row splits (25% of M-tiles to the fp32 path, launched first)
#define YS_QKV 16   // of 64
#define YS_QK  4    // of 16
#define YS_PV  4    // of 16

// ---------------- PTX helpers ------------------------------------------------
__device__ __forceinline__ uint32_t smem_u32(const void* p) {
    uint32_t a;
    asm("{ .reg .u64 t; cvta.to.shared.u64 t, %1; cvt.u32.u64 %0, t; }" : "=r"(a) : "l"(p));
    return a;
}
__device__ __forceinline__ void cp16(uint32_t dst, const void* src) {
    asm volatile("cp.async.cg.shared.global [%0], [%1], 16;" :: "r"(dst), "l"(src));
}
#define CP_COMMIT() asm volatile("cp.async.commit_group;" ::: "memory")

__device__ __forceinline__ void ldm4(uint32_t* r, uint32_t a) {
    asm volatile("ldmatrix.sync.aligned.m8n8.x4.shared.b16 {%0,%1,%2,%3}, [%4];"
                 : "=r"(r[0]), "=r"(r[1]), "=r"(r[2]), "=r"(r[3]) : "r"(a));
}
__device__ __forceinline__ void mma_bf16(float* c, const uint32_t* a, uint32_t b0, uint32_t b1) {
    asm volatile(
        "mma.sync.aligned.m16n8k16.row.col.f32.bf16.bf16.f32 "
        "{%0,%1,%2,%3}, {%4,%5,%6,%7}, {%8,%9}, {%0,%1,%2,%3};"
        : "+f"(c[0]), "+f"(c[1]), "+f"(c[2]), "+f"(c[3])
        : "r"(a[0]), "r"(a[1]), "r"(a[2]), "r"(a[3]), "r"(b0), "r"(b1));
}

__device__ __forceinline__ void split_store(float v, bf16* hi, bf16* lo, size_t o) {
    bf16 h = __float2bfloat16(v);
    hi[o] = h;
    lo[o] = __float2bfloat16(v - __bfloat162float(h));
}

// ---------------- SMEM layout (mma path) -------------------------------------
#define ROWB     80
#define ARR_B    (128 * ROWB)     // 10240
#define STG_B    (4 * ARR_B)      // 40960
#define SM_TOTAL (2 * STG_B)      // 81920 (SIMT path uses 17KB of the same buf)

// ---------------- unified per-element output writer --------------------------
// MODE 0: QKV (z: 0->Q, 1->K, 2->V-transposed) : split bf16 + fp32 copies
// MODE 1: QK  (z=batch) : g_S = v/32 (fp32)
// MODE 2: PV  (z=batch) : out = v (fp32)
template <int MODE>
__device__ __forceinline__ void put_elem(int z, int gr, int gc, float v, float* outp) {
    if (MODE == 0) {
        if (z == 2) {
            const int b = gr >> 11, t = gr & 2047;
            const size_t o = ((size_t)(b * 1024 + gc)) * 2048 + t;
            split_store(v, g_Vthi, g_Vtlo, o);
            g_Vtf[o] = v;
        } else if (z == 0) {
            const size_t o = (size_t)gr * 1024 + gc;
            split_store(v, g_Qhi, g_Qlo, o);
            g_Qf[o] = v;
        } else {
            const size_t o = (size_t)gr * 1024 + gc;
            split_store(v, g_Khi, g_Klo, o);
            g_Kf[o] = v;
        }
    } else if (MODE == 1) {
        g_S[((size_t)z << 22) + (size_t)gr * 2048 + gc] = v * 0.03125f;
    } else {
        outp[((size_t)z << 21) + (size_t)gr * 1024 + gc] = v;
    }
}

// ---------------- mma GEMM body ----------------------------------------------
template <int MODE>
__device__ __forceinline__ void mma_body(
    const bf16* __restrict__ Ah, const bf16* __restrict__ Al, int lda,
    const bf16* __restrict__ Bh, const bf16* __restrict__ Bl, int ldb,
    int K, float* __restrict__ outp)
{
    extern __shared__ char sm[];
    const uint32_t smb = smem_u32(sm);
    const int tid = threadIdx.x, lane = tid & 31, wid = tid >> 5;
    const int wm = wid & 1, wn = wid >> 1;          // warp tile: 64x32
    const int row0 = blockIdx.y * 128, col0 = blockIdx.x * 128;

    float acc[4][4][4];
    #pragma unroll
    for (int i = 0; i < 4; ++i)
        #pragma unroll
        for (int j = 0; j < 4; ++j)
            #pragma unroll
            for (int k = 0; k < 4; ++k) acc[i][j][k] = 0.f;

    const int lr = tid >> 2;
    const int lk = (tid & 3) * 8;
    const uint32_t soff = lr * ROWB + lk * 2;
    const bf16* pa  = Ah + (size_t)(row0 + lr) * lda + lk;
    const bf16* pal = Al + (size_t)(row0 + lr) * lda + lk;
    const bf16* pb  = Bh + (size_t)(col0 + lr) * ldb + lk;
    const bf16* pbl = Bl + (size_t)(col0 + lr) * ldb + lk;

    auto load_stage = [&](int sbuf, int k0) {
        uint32_t b = smb + sbuf * STG_B + soff;
        cp16(b,                         pa  + k0);
        cp16(b + 64 * ROWB,             pa  + k0 + (size_t)64 * lda);
        cp16(b + ARR_B,                 pal + k0);
        cp16(b + ARR_B + 64 * ROWB,     pal + k0 + (size_t)64 * lda);
        cp16(b + 2 * ARR_B,             pb  + k0);
        cp16(b + 2 * ARR_B + 64 * ROWB, pb  + k0 + (size_t)64 * ldb);
        cp16(b + 3 * ARR_B,             pbl + k0);
        cp16(b + 3 * ARR_B + 64 * ROWB, pbl + k0 + (size_t)64 * ldb);
        CP_COMMIT();
    };

    const int ns = K >> 5;
    load_stage(0, 0);

    const uint32_t a_off = (wm * 64 + (lane & 15)) * ROWB + (lane >> 4) * 16;
    const uint32_t b_off = (wn * 32 + (lane & 7) + ((lane >> 4) << 3)) * ROWB
                         + ((lane >> 3) & 1) * 16;

    for (int s = 0; s < ns; ++s) {
        if (s + 1 < ns) {
            load_stage((s + 1) & 1, (s + 1) * 32);
            asm volatile("cp.async.wait_group 1;" ::: "memory");
        } else {
            asm volatile("cp.async.wait_group 0;" ::: "memory");
        }
        __syncthreads();

        const uint32_t sb = smb + (s & 1) * STG_B;
        #pragma unroll
        for (int ks = 0; ks < 2; ++ks) {
            const uint32_t ab = sb + a_off + ks * 32;
            const uint32_t bb = sb + 2 * ARR_B + b_off + ks * 32;
            uint32_t ah[4][4], al[4][4], bh[2][4], bl[2][4];
            #pragma unroll
            for (int mt = 0; mt < 4; ++mt) {
                ldm4(ah[mt], ab + mt * 16 * ROWB);
                ldm4(al[mt], ab + ARR_B + mt * 16 * ROWB);
            }
            #pragma unroll
            for (int bt = 0; bt < 2; ++bt) {
                ldm4(bh[bt], bb + bt * 16 * ROWB);
                ldm4(bl[bt], bb + ARR_B + bt * 16 * ROWB);
            }
            #pragma unroll
            for (int mt = 0; mt < 4; ++mt)
                #pragma unroll
                for (int nt = 0; nt < 4; ++nt) {
                    const int bt = nt >> 1, h = (nt & 1) * 2;
                    mma_bf16(acc[mt][nt], ah[mt], bh[bt][h], bh[bt][h + 1]);
                    mma_bf16(acc[mt][nt], ah[mt], bl[bt][h], bl[bt][h + 1]);
                    mma_bf16(acc[mt][nt], al[mt], bh[bt][h], bh[bt][h + 1]);
                }
        }
        __syncthreads();
    }

    const int z = blockIdx.z;
    const int gr0 = row0 + wm * 64 + (lane >> 2);
    const int gc0 = col0 + wn * 32 + (lane & 3) * 2;

    #pragma unroll
    for (int mt = 0; mt < 4; ++mt)
        #pragma unroll
        for (int nt = 0; nt < 4; ++nt) {
            const int gr = gr0 + mt * 16;
            const int gc = gc0 + nt * 8;
            const float* c = acc[mt][nt];
            put_elem<MODE>(z, gr,     gc,     c[0], outp);
            put_elem<MODE>(z, gr,     gc + 1, c[1], outp);
            put_elem<MODE>(z, gr + 8, gc,     c[2], outp);
            put_elem<MODE>(z, gr + 8, gc + 1, c[3], outp);
        }
}

// ---------------- SIMT fp32 NT GEMM body (R1 port, fp32-exact) ---------------
template <int MODE>
__device__ __forceinline__ void simt_body(
    const float* __restrict__ A, int lda,
    const float* __restrict__ B, int ldb,
    int K, float* __restrict__ outp)
{
    extern __shared__ char sm[];
    float* As = (float*)sm;              // [16][132]
    float* Bs = As + 16 * 132;           // [16][132]

    const int tid = threadIdx.x;
    const int tx = tid & 15, ty = tid >> 4;
    const int row0 = blockIdx.y * 128, col0 = blockIdx.x * 128;
    const int z = blockIdx.z;

    const int lr = tid >> 2;
    const int lc = (tid & 3) << 2;
    const float* Ap = A + (size_t)(row0 + lr) * lda + lc;
    const float* Bp = B + (size_t)(col0 + lr) * ldb + lc;

    float acc[8][8] = {};

    for (int k0 = 0; k0 < K; k0 += 16) {
        float4 a0 = *(const float4*)(Ap + k0);
        float4 a1 = *(const float4*)(Ap + (size_t)64 * lda + k0);
        float4 b0 = *(const float4*)(Bp + k0);
        float4 b1 = *(const float4*)(Bp + (size_t)64 * ldb + k0);

        __syncthreads();
        As[(lc + 0) * 132 + lr] = a0.x; As[(lc + 1) * 132 + lr] = a0.y;
        As[(lc + 2) * 132 + lr] = a0.z; As[(lc + 3) * 132 + lr] = a0.w;
        As[(lc + 0) * 132 + lr + 64] = a1.x; As[(lc + 1) * 132 + lr + 64] = a1.y;
        As[(lc + 2) * 132 + lr + 64] = a1.z; As[(lc + 3) * 132 + lr + 64] = a1.w;
        Bs[(lc + 0) * 132 + lr] = b0.x; Bs[(lc + 1) * 132 + lr] = b0.y;
        Bs[(lc + 2) * 132 + lr] = b0.z; Bs[(lc + 3) * 132 + lr] = b0.w;
        Bs[(lc + 0) * 132 + lr + 64] = b1.x; Bs[(lc + 1) * 132 + lr + 64] = b1.y;
        Bs[(lc + 2) * 132 + lr + 64] = b1.z; Bs[(lc + 3) * 132 + lr + 64] = b1.w;
        __syncthreads();

        #pragma unroll
        for (int kk = 0; kk < 16; ++kk) {
            float4 al = *(const float4*)&As[kk * 132 + ty * 8];
            float4 ah = *(const float4*)&As[kk * 132 + ty * 8 + 4];
            float4 bl = *(const float4*)&Bs[kk * 132 + tx * 8];
            float4 bh = *(const float4*)&Bs[kk * 132 + tx * 8 + 4];
            float af[8] = {al.x, al.y, al.z, al.w, ah.x, ah.y, ah.z, ah.w};
            float bf[8] = {bl.x, bl.y, bl.z, bl.w, bh.x, bh.y, bh.z, bh.w};
            #pragma unroll
            for (int i = 0; i < 8; ++i)
                #pragma unroll
                for (int j = 0; j < 8; ++j)
                    acc[i][j] += af[i] * bf[j];
        }
    }

    #pragma unroll
    for (int i = 0; i < 8; ++i)
        #pragma unroll
        for (int j = 0; j < 8; ++j)
            put_elem<MODE>(z, row0 + ty * 8 + i, col0 + tx * 8 + j, acc[i][j], outp);
}

// ---------------- hybrid kernels ---------------------------------------------
__global__ void __launch_bounds__(256)
qkv_kernel(const float* __restrict__ x, const float* __restrict__ Wq,
           const float* __restrict__ Wk, const float* __restrict__ Wv)
{
    const int z = blockIdx.z;
    if (blockIdx.y < YS_QKV) {
        const float* W = (z == 0) ? Wq : (z == 1) ? Wk : Wv;
        simt_body<0>(x, 1024, W, 1024, 1024, nullptr);
    } else {
        mma_body<0>(g_xhi, g_xlo, 1024,
                    g_Whi + (size_t)z * 1024 * 1024, g_Wlo + (size_t)z * 1024 * 1024, 1024,
                    1024, nullptr);
    }
}

__global__ void __launch_bounds__(256)
qk_kernel()
{
    const size_t bo = (size_t)blockIdx.z << 21;   // b*2048*1024
    if (blockIdx.y < YS_QK) {
        simt_body<1>(g_Qf + bo, 1024, g_Kf + bo, 1024, 1024, nullptr);
    } else {
        mma_body<1>(g_Qhi + bo, g_Qlo + bo, 1024,
                    g_Khi + bo, g_Klo + bo, 1024,
                    1024, nullptr);
    }
}

__global__ void __launch_bounds__(256)
pv_kernel(float* __restrict__ out)
{
    const size_t ao = (size_t)blockIdx.z << 22;   // b*2048*2048
    const size_t bo = (size_t)blockIdx.z << 21;   // b*1024*2048
    if (blockIdx.y < YS_PV) {
        simt_body<2>(g_S + ao, 2048, g_Vtf + bo, 2048, 2048, out);
    } else {
        mma_body<2>(g_Phi + ao, g_Plo + ao, 2048,
                    g_Vthi + bo, g_Vtlo + bo, 2048,
                    2048, out);
    }
}

__global__ void __launch_bounds__(256)
convert_kernel(const float* __restrict__ src, bf16* __restrict__ hi,
               bf16* __restrict__ lo, int n4)
{
    int i = blockIdx.x * blockDim.x + threadIdx.x;
    if (i < n4) {
        float4 v = *(const float4*)(src + i * 4);
        float f[4] = {v.x, v.y, v.z, v.w};
        #pragma unroll
        for (int j = 0; j < 4; ++j) {
            bf16 h = __float2bfloat16(f[j]);
            hi[i * 4 + j] = h;
            lo[i * 4 + j] = __float2bfloat16(f[j] - __bfloat162float(h));
        }
    }
}

__global__ void __launch_bounds__(256)
softmax_kernel()
{
    size_t ro = (size_t)blockIdx.x * 2048;
    float* p = g_S + ro;
    const int t = threadIdx.x;
    __shared__ float red[8];

    float v[8];
    float m = -1e30f;
    #pragma unroll
    for (int i = 0; i < 8; ++i) {
        v[i] = p[t + i * 256];
        m = fmaxf(m, v[i]);
    }
    #pragma unroll
    for (int o = 16; o; o >>= 1) m = fmaxf(m, __shfl_xor_sync(0xffffffffu, m, o));
    if ((t & 31) == 0) red[t >> 5] = m;
    __syncthreads();
    m = red[0];
    #pragma unroll
    for (int i = 1; i < 8; ++i) m = fmaxf(m, red[i]);
    __syncthreads();

    float s = 0.f;
    #pragma unroll
    for (int i = 0; i < 8; ++i) {
        v[i] = __expf(v[i] - m);
        s += v[i];
    }
    #pragma unroll
    for (int o = 16; o; o >>= 1) s += __shfl_xor_sync(0xffffffffu, s, o);
    if ((t & 31) == 0) red[t >> 5] = s;
    __syncthreads();
    s = red[0];
    #pragma unroll
    for (int i = 1; i < 8; ++i) s += red[i];

    const float inv = 1.0f / s;
    #pragma unroll
    for (int i = 0; i < 8; ++i) {
        float pv = v[i] * inv;
        size_t o = ro + t + i * 256;
        p[t + i * 256] = pv;                 // fp32 probs for SIMT PV path
        bf16 h = __float2bfloat16(pv);
        g_Phi[o] = h;
        g_Plo[o] = __float2bfloat16(pv - __bfloat162float(h));
    }
}

// ---------------- launch ------------------------------------------------------
extern "C" void kernel_launch(void* const* d_in, const int* in_sizes, int n_in,
                              void* d_out, int out_size)
{
    const float* x  = (const float*)d_in[0];
    const float* Wq = (const float*)d_in[1];
    const float* Wk = (const float*)d_in[2];
    const float* Wv = (const float*)d_in[3];
    float* out = (float*)d_out;

    cudaFuncSetAttribute(qkv_kernel, cudaFuncAttributeMaxDynamicSharedMemorySize, SM_TOTAL);
    cudaFuncSetAttribute(qk_kernel,  cudaFuncAttributeMaxDynamicSharedMemorySize, SM_TOTAL);
    cudaFuncSetAttribute(pv_kernel,  cudaFuncAttributeMaxDynamicSharedMemorySize, SM_TOTAL);

    bf16 *xhi, *xlo, *whi, *wlo;
    cudaGetSymbolAddress((void**)&xhi, g_xhi);
    cudaGetSymbolAddress((void**)&xlo, g_xlo);
    cudaGetSymbolAddress((void**)&whi, g_Whi);
    cudaGetSymbolAddress((void**)&wlo, g_Wlo);

    {
        int n4 = 8192 * 1024 / 4;
        convert_kernel<<<(n4 + 255) / 256, 256>>>(x, xhi, xlo, n4);
    }
    {
        int n4 = 1024 * 1024 / 4;
        convert_kernel<<<(n4 + 255) / 256, 256>>>(Wq, whi, wlo, n4);
        convert_kernel<<<(n4 + 255) / 256, 256>>>(Wk, whi + 1024 * 1024, wlo + 1024 * 1024, n4);
        convert_kernel<<<(n4 + 255) / 256, 256>>>(Wv, whi + 2 * 1024 * 1024, wlo + 2 * 1024 * 1024, n4);
    }

    dim3 g1(8, 64, 3);    // QKV: N=1024/128, M=8192/128 (y<16 -> SIMT)
    qkv_kernel<<<g1, 256, SM_TOTAL>>>(x, Wq, Wk, Wv);

    dim3 g2(16, 16, 4);   // QK: 2048x2048 per batch (y<4 -> SIMT)
    qk_kernel<<<g2, 256, SM_TOTAL>>>();

    softmax_kernel<<<4 * 2048, 256>>>();

    dim3 g3(8, 16, 4);    // PV: 2048x1024, K=2048 (y<4 -> SIMT)
    pv_kernel<<<g3, 256, SM_TOTAL>>>(out);
}